// round 5
// baseline (speedup 1.0000x reference)
#include <cuda_runtime.h>
#include <cuda_bf16.h>
#include <math.h>
#include <stdint.h>

#define BATCH   8
#define SEQ     2048
#define NTOK    16384
#define FDIM    128
#define DMODEL  512
#define DINNER  1024
#define NLAYERS 4
#define VOCAB   256
#define NHEADS  384

// ---------------- scratch (device globals; no allocs) ----------------
// Buffers feeding GEMM A/B operands hold tf32-bit patterns (stored as float).
__device__ float g_x [NTOK * DMODEL];                        // residual (fp32)
__device__ float g_n [NTOK * DMODEL];                        // LN out (tf32 bits)
__device__ float g_h [NTOK * DINNER];                        // GLU out (tf32 bits)
__device__ float g_fr[NTOK * FDIM];                          // frames (tf32 bits)
__device__ float g_bt_inproj[DMODEL * FDIM];                 // tf32 bits
__device__ float g_bt_win   [NLAYERS * 2 * DINNER * DMODEL]; // tf32 bits
__device__ float g_bt_wout  [NLAYERS * DMODEL * DINNER];     // tf32 bits
__device__ float g_wh_t     [NHEADS * DMODEL];               // tf32 bits
__device__ float g_bh       [NHEADS];

// ---------------- helpers ----------------
__device__ __forceinline__ uint32_t smem_u32(const void* p) {
    uint32_t a;
    asm("{ .reg .u64 t; cvta.to.shared.u64 t, %1; cvt.u32.u64 %0, t; }" : "=r"(a) : "l"(p));
    return a;
}
__device__ __forceinline__ uint32_t f2t(float x) {   // fp32 -> tf32 (RNA)
    uint32_t r; asm("cvt.rna.tf32.f32 %0, %1;" : "=r"(r) : "f"(x)); return r;
}
__device__ __forceinline__ float f2tf(float x) { return __uint_as_float(f2t(x)); }
__device__ __forceinline__ void mma8(float* d, const uint32_t* a, const uint32_t* b) {
    asm volatile("mma.sync.aligned.m16n8k8.row.col.f32.tf32.tf32.f32 "
                 "{%0,%1,%2,%3}, {%4,%5,%6,%7}, {%8,%9}, {%0,%1,%2,%3};"
                 : "+f"(d[0]), "+f"(d[1]), "+f"(d[2]), "+f"(d[3])
                 : "r"(a[0]), "r"(a[1]), "r"(a[2]), "r"(a[3]), "r"(b[0]), "r"(b[1]));
}
__device__ __forceinline__ void cpa16(uint32_t s, const void* g) {
    asm volatile("cp.async.cg.shared.global [%0], [%1], 16;" :: "r"(s), "l"(g));
}
#define CP_COMMIT() asm volatile("cp.async.commit_group;")
#define CP_WAIT1()  asm volatile("cp.async.wait_group 1;")
#define CP_WAIT0()  asm volatile("cp.async.wait_group 0;")

#define LDK 40                 // row stride in floats: 16B-aligned, conflict-free frags
#define TILE_F (128 * LDK)
#define STAGE_F (2 * TILE_F)
#define SMEM_BYTES (2 * STAGE_F * 4)   // 81920

// ---------------- tf32 mma.sync GEMM, cp.async double-buffered ----------------
// A and Bt hold tf32-bit patterns; no conversion in the mainloop.
// MODE 1: C = acc + bias + pos_emb[s,col]          (fp32 out)
// MODE 2: C = (aux + acc + bias) * decay(s)        (fp32 out, in-place residual)
// MODE 3: heads: mask ? acc+bias : 0; split frame/sym (fp32 out)
// MODE 4: GLU fused: h = u*silu(g), stored as tf32 bits
template<int MODE>
__global__ __launch_bounds__(256, 2)
void gemm_mma(const float* __restrict__ A, const float* __restrict__ Bt,
              const float* __restrict__ bias, float* __restrict__ C,
              int K, int Nfull,
              const float* __restrict__ aux, const int* __restrict__ mask,
              float* __restrict__ out2)
{
    extern __shared__ float smem[];
    const int tid  = threadIdx.x;
    const int wid  = tid >> 5, lane = tid & 31;
    const int r    = lane >> 2, c = lane & 3;
    const int wm   = (wid & 1) * 64;
    const int wn   = (wid >> 1) * 32;
    const int r0   = blockIdx.y * 128;
    const int c0   = blockIdx.x * ((MODE == 4) ? 64 : 128);

    const int srw = tid >> 3;
    const int sf  = (tid & 7) * 4;

    auto browf = [&](int t) -> int {
        if (MODE == 4) {
            const int wq = t >> 5, i5 = t & 31;
            return c0 + wq * 16 + (i5 & 15) + ((i5 >> 4) ? DINNER : 0);
        }
        return c0 + t;
    };

    const uint32_t sbase = smem_u32(smem);
    const int nch = K >> 5;

    auto stage = [&](int ch, int buf) {
        const int kc = ch << 5;
        const uint32_t aB = sbase + (buf * STAGE_F) * 4;
        const uint32_t bB = aB + TILE_F * 4;
        #pragma unroll
        for (int i = 0; i < 4; i++) {
            const int rw = srw + 32 * i;
            cpa16(aB + (rw * LDK + sf) * 4, A + (size_t)(r0 + rw) * K + kc + sf);
        }
        #pragma unroll
        for (int i = 0; i < 4; i++) {
            const int rw = srw + 32 * i;
            cpa16(bB + (rw * LDK + sf) * 4, Bt + (size_t)browf(rw) * K + kc + sf);
        }
        CP_COMMIT();
    };

    float acc[4][4][4];
    #pragma unroll
    for (int mt = 0; mt < 4; mt++)
        #pragma unroll
        for (int nt = 0; nt < 4; nt++)
            #pragma unroll
            for (int q = 0; q < 4; q++) acc[mt][nt][q] = 0.f;

    stage(0, 0);
    if (nch > 1) stage(1, 1);

    int buf = 0;
    for (int ch = 0; ch < nch; ch++) {
        if (ch + 1 < nch) { CP_WAIT1(); } else { CP_WAIT0(); }
        __syncthreads();

        const uint32_t* As = (const uint32_t*)(smem + buf * STAGE_F);
        const uint32_t* Bs = As + TILE_F;
        #pragma unroll
        for (int ks = 0; ks < 4; ks++) {
            const int kb = ks * 8;
            uint32_t af[4][4], bf[4][2];
            #pragma unroll
            for (int mt = 0; mt < 4; mt++) {
                const uint32_t* p = &As[(wm + mt * 16 + r) * LDK + kb + c];
                af[mt][0] = p[0];
                af[mt][1] = p[8 * LDK];
                af[mt][2] = p[4];
                af[mt][3] = p[8 * LDK + 4];
            }
            #pragma unroll
            for (int nt = 0; nt < 4; nt++) {
                const uint32_t* p = &Bs[(wn + nt * 8 + r) * LDK + kb + c];
                bf[nt][0] = p[0];
                bf[nt][1] = p[4];
            }
            #pragma unroll
            for (int mt = 0; mt < 4; mt++)
                #pragma unroll
                for (int nt = 0; nt < 4; nt++)
                    mma8(acc[mt][nt], af[mt], bf[nt]);
        }
        __syncthreads();
        if (ch + 2 < nch) stage(ch + 2, buf);
        buf ^= 1;
    }

    // ---------------- epilogue ----------------
    if (MODE == 4) {
        const int wq = wid >> 1;
        #pragma unroll
        for (int mt = 0; mt < 4; mt++) {
            #pragma unroll
            for (int h = 0; h < 2; h++) {
                const int row = r0 + wm + mt * 16 + r + h * 8;
                #pragma unroll
                for (int nt = 0; nt < 2; nt++) {
                    const int ucol = c0 + wq * 16 + nt * 8 + 2 * c;
                    float2 bu = *(const float2*)(bias + ucol);
                    float2 bg = *(const float2*)(bias + DINNER + ucol);
                    float ux = acc[mt][nt][2*h+0] + bu.x;
                    float uy = acc[mt][nt][2*h+1] + bu.y;
                    float gx = acc[mt][nt+2][2*h+0] + bg.x;
                    float gy = acc[mt][nt+2][2*h+1] + bg.y;
                    float2 v;
                    v.x = f2tf(ux * gx / (1.0f + __expf(-gx)));
                    v.y = f2tf(uy * gy / (1.0f + __expf(-gy)));
                    *(float2*)(C + (size_t)row * DINNER + ucol) = v;
                }
            }
        }
        return;
    }

    #pragma unroll
    for (int mt = 0; mt < 4; mt++) {
        #pragma unroll
        for (int h = 0; h < 2; h++) {
            const int row = r0 + wm + mt * 16 + r + h * 8;
            const int s   = row & (SEQ - 1);
            float dec = 1.0f, mk = 1.0f;
            if (MODE == 2) dec = (((s + 1) % 10) == 0) ? 0.1f : 1.0f;
            if (MODE == 3) mk  = (mask[row] != 0) ? 1.0f : 0.0f;
            #pragma unroll
            for (int nt = 0; nt < 4; nt++) {
                const int col = c0 + wn + nt * 8 + 2 * c;
                float2 bv = *(const float2*)(bias + col);
                float2 v;
                v.x = acc[mt][nt][2*h+0] + bv.x;
                v.y = acc[mt][nt][2*h+1] + bv.y;
                if (MODE == 1) {
                    float2 p = *(const float2*)(aux + (size_t)s * DMODEL + col);
                    v.x += p.x; v.y += p.y;
                }
                if (MODE == 2) {
                    float2 xv = *(const float2*)(aux + (size_t)row * Nfull + col);
                    v.x = (v.x + xv.x) * dec;
                    v.y = (v.y + xv.y) * dec;
                }
                if (MODE == 3) {
                    v.x *= mk; v.y *= mk;
                    if (col < FDIM)
                        *(float2*)(C + (size_t)row * FDIM + col) = v;
                    else
                        *(float2*)(out2 + (size_t)row * VOCAB + (col - FDIM)) = v;
                } else {
                    *(float2*)(C + (size_t)row * Nfull + col) = v;
                }
            }
        }
    }
}

// ---------------- weight transpose + tf32 convert ----------------
__global__ void transpose_k(const float* __restrict__ in, float* __restrict__ out, int K, int N)
{
    __shared__ float t[32][33];
    const int n0 = blockIdx.x * 32, k0 = blockIdx.y * 32;
    const int x = threadIdx.x, y = threadIdx.y;
    #pragma unroll
    for (int i = 0; i < 32; i += 8)
        t[y + i][x] = in[(size_t)(k0 + y + i) * N + n0 + x];
    __syncthreads();
    #pragma unroll
    for (int i = 0; i < 32; i += 8)
        out[(size_t)(n0 + y + i) * K + k0 + x] = f2tf(t[x][y + i]);
}

// ---------------- pack head weights transposed (tf32 bits) ----------------
__global__ void pack_heads_t(const float* __restrict__ Wf, const float* __restrict__ bf,
                             const float* __restrict__ Ws, const float* __restrict__ bs,
                             float* __restrict__ wht, float* __restrict__ bh)
{
    const int i = blockIdx.x * 256 + threadIdx.x;
    if (i < DMODEL * NHEADS) {
        const int r = i / NHEADS, c = i % NHEADS;
        wht[(size_t)c * DMODEL + r] =
            f2tf((c < FDIM) ? Wf[r * FDIM + c] : Ws[r * VOCAB + (c - FDIM)]);
    }
    if (i < NHEADS) bh[i] = (i < FDIM) ? bf[i] : bs[i - FDIM];
}

// ---------------- frames -> tf32 bits ----------------
__global__ void conv_tf32(const float* __restrict__ in, float* __restrict__ out, int n4)
{
    const int i = blockIdx.x * 256 + threadIdx.x;
    if (i < n4) {
        float4 v = ((const float4*)in)[i];
        float4 r;
        r.x = f2tf(v.x); r.y = f2tf(v.y); r.z = f2tf(v.z); r.w = f2tf(v.w);
        ((float4*)out)[i] = r;
    }
}

// ---------------- LayerNorm: one warp per row; output tf32 bits ----------------
__global__ __launch_bounds__(256)
void ln_kernel(const float* __restrict__ x, const float* __restrict__ sc,
               const float* __restrict__ bi, float* __restrict__ out)
{
    const int row  = blockIdx.x * 8 + threadIdx.y;
    const int lane = threadIdx.x;
    const float4* xr = (const float4*)(x + (size_t)row * DMODEL);
    float4 v[4]; float s = 0.f;
    #pragma unroll
    for (int i = 0; i < 4; i++) { v[i] = xr[lane + 32*i]; s += v[i].x + v[i].y + v[i].z + v[i].w; }
    #pragma unroll
    for (int o = 16; o > 0; o >>= 1) s += __shfl_xor_sync(0xffffffffu, s, o);
    const float mu = s * (1.0f / DMODEL);
    float q = 0.f;
    #pragma unroll
    for (int i = 0; i < 4; i++) {
        float d;
        d = v[i].x - mu; q += d*d;  d = v[i].y - mu; q += d*d;
        d = v[i].z - mu; q += d*d;  d = v[i].w - mu; q += d*d;
    }
    #pragma unroll
    for (int o = 16; o > 0; o >>= 1) q += __shfl_xor_sync(0xffffffffu, q, o);
    const float inv = rsqrtf(q * (1.0f / DMODEL) + 1e-5f);
    const float4* s4 = (const float4*)sc;
    const float4* b4 = (const float4*)bi;
    float4* o4 = (float4*)(out + (size_t)row * DMODEL);
    #pragma unroll
    for (int i = 0; i < 4; i++) {
        const int cc = lane + 32*i;
        float4 sv = s4[cc], bv = b4[cc], rr;
        rr.x = f2tf((v[i].x - mu) * inv * sv.x + bv.x);
        rr.y = f2tf((v[i].y - mu) * inv * sv.y + bv.y);
        rr.z = f2tf((v[i].z - mu) * inv * sv.z + bv.z);
        rr.w = f2tf((v[i].w - mu) * inv * sv.w + bv.w);
        o4[cc] = rr;
    }
}

// -----------------------------------------------------------------------------
extern "C" void kernel_launch(void* const* d_in, const int* in_sizes, int n_in,
                              void* d_out, int out_size)
{
    const float* frames    = (const float*)d_in[0];
    const int*   mask      = (const int*)d_in[1];
    const float* W_in_proj = (const float*)d_in[2];
    const float* b_in_proj = (const float*)d_in[3];
    const float* pos_emb   = (const float*)d_in[4];
    const float* ln_scale  = (const float*)d_in[5];
    const float* ln_bias   = (const float*)d_in[6];
    const float* W_in      = (const float*)d_in[7];
    const float* b_in      = (const float*)d_in[8];
    const float* W_out     = (const float*)d_in[9];
    const float* b_out     = (const float*)d_in[10];
    const float* fn_scale  = (const float*)d_in[11];
    const float* fn_bias   = (const float*)d_in[12];
    const float* W_frame   = (const float*)d_in[13];
    const float* b_frame   = (const float*)d_in[14];
    const float* W_sym     = (const float*)d_in[15];
    const float* b_sym     = (const float*)d_in[16];

    float *px, *pn, *ph, *pfr, *pbtP, *pbtI, *pbtO, *pwht, *pbh;
    cudaGetSymbolAddress((void**)&px,   g_x);
    cudaGetSymbolAddress((void**)&pn,   g_n);
    cudaGetSymbolAddress((void**)&ph,   g_h);
    cudaGetSymbolAddress((void**)&pfr,  g_fr);
    cudaGetSymbolAddress((void**)&pbtP, g_bt_inproj);
    cudaGetSymbolAddress((void**)&pbtI, g_bt_win);
    cudaGetSymbolAddress((void**)&pbtO, g_bt_wout);
    cudaGetSymbolAddress((void**)&pwht, g_wh_t);
    cudaGetSymbolAddress((void**)&pbh,  g_bh);

    float* out_frame = (float*)d_out;
    float* out_sym   = (float*)d_out + (size_t)NTOK * FDIM;

    cudaFuncSetAttribute(gemm_mma<1>, cudaFuncAttributeMaxDynamicSharedMemorySize, SMEM_BYTES);
    cudaFuncSetAttribute(gemm_mma<2>, cudaFuncAttributeMaxDynamicSharedMemorySize, SMEM_BYTES);
    cudaFuncSetAttribute(gemm_mma<3>, cudaFuncAttributeMaxDynamicSharedMemorySize, SMEM_BYTES);
    cudaFuncSetAttribute(gemm_mma<4>, cudaFuncAttributeMaxDynamicSharedMemorySize, SMEM_BYTES);

    // ---- weight & input prep (tf32 bits) ----
    {
        dim3 b(32, 8);
        transpose_k<<<dim3(DMODEL/32, FDIM/32), b>>>(W_in_proj, pbtP, FDIM, DMODEL);
        for (int l = 0; l < NLAYERS; l++) {
            transpose_k<<<dim3(2*DINNER/32, DMODEL/32), b>>>(
                W_in + (size_t)l * DMODEL * 2 * DINNER,
                pbtI + (size_t)l * 2 * DINNER * DMODEL, DMODEL, 2*DINNER);
            transpose_k<<<dim3(DMODEL/32, DINNER/32), b>>>(
                W_out + (size_t)l * DINNER * DMODEL,
                pbtO + (size_t)l * DMODEL * DINNER, DINNER, DMODEL);
        }
        pack_heads_t<<<(DMODEL*NHEADS + 255)/256, 256>>>(W_frame, b_frame, W_sym, b_sym, pwht, pbh);
        conv_tf32<<<(NTOK*FDIM/4 + 255)/256, 256>>>(frames, pfr, NTOK*FDIM/4);
    }

    const dim3 lnb(32, 8);
    const int  lng = NTOK / 8;

    // 1) in_proj + pos_emb
    gemm_mma<1><<<dim3(DMODEL/128, NTOK/128), 256, SMEM_BYTES>>>(
        pfr, pbtP, b_in_proj, px, FDIM, DMODEL, pos_emb, nullptr, nullptr);

    // 2) layers: LN -> fused GEMM+GLU -> GEMM+residual
    for (int l = 0; l < NLAYERS; l++) {
        ln_kernel<<<lng, lnb>>>(px, ln_scale + l*DMODEL, ln_bias + l*DMODEL, pn);

        gemm_mma<4><<<dim3(DINNER/64, NTOK/128), 256, SMEM_BYTES>>>(
            pn, pbtI + (size_t)l * 2*DINNER*DMODEL,
            b_in + (size_t)l * 2*DINNER, ph, DMODEL, DINNER,
            nullptr, nullptr, nullptr);

        gemm_mma<2><<<dim3(DMODEL/128, NTOK/128), 256, SMEM_BYTES>>>(
            ph, pbtO + (size_t)l * DMODEL*DINNER,
            b_out + (size_t)l * DMODEL, px, DINNER, DMODEL,
            px, nullptr, nullptr);
    }

    // 3) final LN
    ln_kernel<<<lng, lnb>>>(px, fn_scale, fn_bias, pn);

    // 4) heads
    gemm_mma<3><<<dim3(NHEADS/128, NTOK/128), 256, SMEM_BYTES>>>(
        pn, pwht, pbh, out_frame, DMODEL, NHEADS,
        nullptr, mask, out_sym);
}

// round 6
// speedup vs baseline: 1.7763x; 1.7763x over previous
#include <cuda_runtime.h>
#include <cuda_fp16.h>
#include <math.h>
#include <stdint.h>

#define BATCH   8
#define SEQ     2048
#define NTOK    16384
#define FDIM    128
#define DMODEL  512
#define DINNER  1024
#define NLAYERS 4
#define VOCAB   256
#define NHEADS  384

// ---------------- scratch (device globals; no allocs) ----------------
__device__ float  g_x [NTOK * DMODEL];                        // residual (fp32)
__device__ __half g_n [NTOK * DMODEL];                        // LN out
__device__ __half g_h [NTOK * DINNER];                        // GLU out
__device__ __half g_fr[NTOK * FDIM];                          // frames
__device__ __half g_bt_inproj[DMODEL * FDIM];
__device__ __half g_bt_win   [NLAYERS * 2 * DINNER * DMODEL];
__device__ __half g_bt_wout  [NLAYERS * DMODEL * DINNER];
__device__ __half g_wh_t     [NHEADS * DMODEL];
__device__ float  g_bh       [NHEADS];

// ---------------- helpers ----------------
__device__ __forceinline__ uint32_t smem_u32(const void* p) {
    uint32_t a;
    asm("{ .reg .u64 t; cvta.to.shared.u64 t, %1; cvt.u32.u64 %0, t; }" : "=r"(a) : "l"(p));
    return a;
}
__device__ __forceinline__ void mma16(float* d, const uint32_t* a, const uint32_t* b) {
    asm volatile("mma.sync.aligned.m16n8k16.row.col.f32.f16.f16.f32 "
                 "{%0,%1,%2,%3}, {%4,%5,%6,%7}, {%8,%9}, {%0,%1,%2,%3};"
                 : "+f"(d[0]), "+f"(d[1]), "+f"(d[2]), "+f"(d[3])
                 : "r"(a[0]), "r"(a[1]), "r"(a[2]), "r"(a[3]), "r"(b[0]), "r"(b[1]));
}
__device__ __forceinline__ void cpa16(uint32_t s, const void* g) {
    asm volatile("cp.async.cg.shared.global [%0], [%1], 16;" :: "r"(s), "l"(g));
}
#define CP_COMMIT() asm volatile("cp.async.commit_group;")
#define CP_WAIT2()  asm volatile("cp.async.wait_group 2;")
#define CP_WAIT1()  asm volatile("cp.async.wait_group 1;")
#define CP_WAIT0()  asm volatile("cp.async.wait_group 0;")

#define LDKH 40                    // row stride in halfs (80B: 16B-aligned, conflict-free)
#define LDKW 20                    // row stride in u32 (half2) units
#define TILE_B (128 * LDKH * 2)    // 10240 bytes per staged matrix
#define STAGE_B (2 * TILE_B)       // 20480 bytes (A+B)
#define NSTAGE 3
#define SMEM_BYTES (NSTAGE * STAGE_B)   // 61440

// ---------------- fp16 mma.sync GEMM, cp.async 3-stage pipeline ----------------
// MODE 1: C = acc + bias + pos_emb[s,col]          (fp32 out)
// MODE 2: C = (aux + acc + bias) * decay(s)        (fp32 out, in-place residual)
// MODE 3: heads: mask ? acc+bias : 0; split frame/sym (fp32 out)
// MODE 4: GLU fused: h = u*silu(g), stored as half (C recast to __half*)
template<int MODE>
__global__ __launch_bounds__(256, 2)
void gemm_mma(const __half* __restrict__ A, const __half* __restrict__ Bt,
              const float* __restrict__ bias, float* __restrict__ C,
              int K, int Nfull,
              const float* __restrict__ aux, const int* __restrict__ mask,
              float* __restrict__ out2)
{
    extern __shared__ uint32_t smem[];
    const int tid  = threadIdx.x;
    const int wid  = tid >> 5, lane = tid & 31;
    const int r    = lane >> 2, c = lane & 3;
    const int wm   = (wid & 1) * 64;
    const int wn   = (wid >> 1) * 32;
    const int r0   = blockIdx.y * 128;
    const int c0   = blockIdx.x * ((MODE == 4) ? 64 : 128);

    // staging: 128 rows x 32 halfs per tile; 16B (8 halfs) per cp.async
    const int srw = tid >> 2;            // row 0..63 (+64 second iter)
    const int sfh = (tid & 3) * 8;       // k-half offset 0,8,16,24

    auto browf = [&](int t) -> int {     // staged B row -> global Bt row
        if (MODE == 4) {
            const int wq = t >> 5, i5 = t & 31;
            return c0 + wq * 16 + (i5 & 15) + ((i5 >> 4) ? DINNER : 0);
        }
        return c0 + t;
    };

    const uint32_t sbase = smem_u32(smem);
    const int nch = K >> 5;

    auto stage = [&](int ch, int buf) {
        const int kc = ch << 5;
        const uint32_t aB = sbase + buf * STAGE_B;
        const uint32_t bB = aB + TILE_B;
        #pragma unroll
        for (int i = 0; i < 2; i++) {
            const int rw = srw + 64 * i;
            cpa16(aB + rw * (LDKH*2) + (tid & 3) * 16,
                  A + (size_t)(r0 + rw) * K + kc + sfh);
        }
        #pragma unroll
        for (int i = 0; i < 2; i++) {
            const int rw = srw + 64 * i;
            cpa16(bB + rw * (LDKH*2) + (tid & 3) * 16,
                  Bt + (size_t)browf(rw) * K + kc + sfh);
        }
        CP_COMMIT();
    };

    float acc[4][4][4];
    #pragma unroll
    for (int mt = 0; mt < 4; mt++)
        #pragma unroll
        for (int nt = 0; nt < 4; nt++)
            #pragma unroll
            for (int q = 0; q < 4; q++) acc[mt][nt][q] = 0.f;

    stage(0, 0);
    if (nch > 1) stage(1, 1);

    for (int ch = 0; ch < nch; ch++) {
        const int buf = ch % NSTAGE;
        if (ch + 2 < nch) { stage(ch + 2, (ch + 2) % NSTAGE); CP_WAIT2(); }
        else if (ch + 1 < nch) { CP_WAIT1(); }
        else { CP_WAIT0(); }
        __syncthreads();

        const uint32_t* As = smem + buf * (STAGE_B / 4);
        const uint32_t* Bs = As + TILE_B / 4;
        #pragma unroll
        for (int ks = 0; ks < 2; ks++) {            // 2 x K=16 steps
            const int kb2 = ks * 8;                 // u32 offset within row
            uint32_t af[4][4], bf[4][2];
            #pragma unroll
            for (int mt = 0; mt < 4; mt++) {
                const uint32_t* p = &As[(wm + mt * 16 + r) * LDKW + kb2 + c];
                af[mt][0] = p[0];
                af[mt][1] = p[8 * LDKW];
                af[mt][2] = p[4];
                af[mt][3] = p[8 * LDKW + 4];
            }
            #pragma unroll
            for (int nt = 0; nt < 4; nt++) {
                const uint32_t* p = &Bs[(wn + nt * 8 + r) * LDKW + kb2 + c];
                bf[nt][0] = p[0];
                bf[nt][1] = p[4];
            }
            #pragma unroll
            for (int mt = 0; mt < 4; mt++)
                #pragma unroll
                for (int nt = 0; nt < 4; nt++)
                    mma16(acc[mt][nt], af[mt], bf[nt]);
        }
        __syncthreads();
    }

    // ---------------- epilogue ----------------
    if (MODE == 4) {
        __half* Ch = (__half*)C;
        const int wq = wid >> 1;
        #pragma unroll
        for (int mt = 0; mt < 4; mt++) {
            #pragma unroll
            for (int h = 0; h < 2; h++) {
                const int row = r0 + wm + mt * 16 + r + h * 8;
                #pragma unroll
                for (int nt = 0; nt < 2; nt++) {
                    const int ucol = c0 + wq * 16 + nt * 8 + 2 * c;
                    float2 bu = *(const float2*)(bias + ucol);
                    float2 bg = *(const float2*)(bias + DINNER + ucol);
                    float ux = acc[mt][nt][2*h+0] + bu.x;
                    float uy = acc[mt][nt][2*h+1] + bu.y;
                    float gx = acc[mt][nt+2][2*h+0] + bg.x;
                    float gy = acc[mt][nt+2][2*h+1] + bg.y;
                    float vx = ux * gx / (1.0f + __expf(-gx));
                    float vy = uy * gy / (1.0f + __expf(-gy));
                    *(__half2*)(Ch + (size_t)row * DINNER + ucol) =
                        __floats2half2_rn(vx, vy);
                }
            }
        }
        return;
    }

    #pragma unroll
    for (int mt = 0; mt < 4; mt++) {
        #pragma unroll
        for (int h = 0; h < 2; h++) {
            const int row = r0 + wm + mt * 16 + r + h * 8;
            const int s   = row & (SEQ - 1);
            float dec = 1.0f, mk = 1.0f;
            if (MODE == 2) dec = (((s + 1) % 10) == 0) ? 0.1f : 1.0f;
            if (MODE == 3) mk  = (mask[row] != 0) ? 1.0f : 0.0f;
            #pragma unroll
            for (int nt = 0; nt < 4; nt++) {
                const int col = c0 + wn + nt * 8 + 2 * c;
                float2 bv = *(const float2*)(bias + col);
                float2 v;
                v.x = acc[mt][nt][2*h+0] + bv.x;
                v.y = acc[mt][nt][2*h+1] + bv.y;
                if (MODE == 1) {
                    float2 p = *(const float2*)(aux + (size_t)s * DMODEL + col);
                    v.x += p.x; v.y += p.y;
                }
                if (MODE == 2) {
                    float2 xv = *(const float2*)(aux + (size_t)row * Nfull + col);
                    v.x = (v.x + xv.x) * dec;
                    v.y = (v.y + xv.y) * dec;
                }
                if (MODE == 3) {
                    v.x *= mk; v.y *= mk;
                    if (col < FDIM)
                        *(float2*)(C + (size_t)row * FDIM + col) = v;
                    else
                        *(float2*)(out2 + (size_t)row * VOCAB + (col - FDIM)) = v;
                } else {
                    *(float2*)(C + (size_t)row * Nfull + col) = v;
                }
            }
        }
    }
}

// ---------------- weight transpose -> half: out[N,K] = half(in[K,N]^T) ----------------
__global__ void transpose_k(const float* __restrict__ in, __half* __restrict__ out, int K, int N)
{
    __shared__ float t[32][33];
    const int n0 = blockIdx.x * 32, k0 = blockIdx.y * 32;
    const int x = threadIdx.x, y = threadIdx.y;
    #pragma unroll
    for (int i = 0; i < 32; i += 8)
        t[y + i][x] = in[(size_t)(k0 + y + i) * N + n0 + x];
    __syncthreads();
    #pragma unroll
    for (int i = 0; i < 32; i += 8)
        out[(size_t)(n0 + y + i) * K + k0 + x] = __float2half_rn(t[x][y + i]);
}

// ---------------- pack head weights transposed -> half ----------------
__global__ void pack_heads_t(const float* __restrict__ Wf, const float* __restrict__ bf,
                             const float* __restrict__ Ws, const float* __restrict__ bs,
                             __half* __restrict__ wht, float* __restrict__ bh)
{
    const int i = blockIdx.x * 256 + threadIdx.x;
    if (i < DMODEL * NHEADS) {
        const int r = i / NHEADS, c = i % NHEADS;
        wht[(size_t)c * DMODEL + r] =
            __float2half_rn((c < FDIM) ? Wf[r * FDIM + c] : Ws[r * VOCAB + (c - FDIM)]);
    }
    if (i < NHEADS) bh[i] = (i < FDIM) ? bf[i] : bs[i - FDIM];
}

// ---------------- frames -> half ----------------
__global__ void conv_h(const float* __restrict__ in, __half* __restrict__ out, int n4)
{
    const int i = blockIdx.x * 256 + threadIdx.x;
    if (i < n4) {
        float4 v = ((const float4*)in)[i];
        __half2* o = (__half2*)out + 2 * i;
        o[0] = __floats2half2_rn(v.x, v.y);
        o[1] = __floats2half2_rn(v.z, v.w);
    }
}

// ---------------- LayerNorm: one warp per row; half output ----------------
__global__ __launch_bounds__(256)
void ln_kernel(const float* __restrict__ x, const float* __restrict__ sc,
               const float* __restrict__ bi, __half* __restrict__ out)
{
    const int row  = blockIdx.x * 8 + threadIdx.y;
    const int lane = threadIdx.x;
    const float4* xr = (const float4*)(x + (size_t)row * DMODEL);
    float4 v[4]; float s = 0.f;
    #pragma unroll
    for (int i = 0; i < 4; i++) { v[i] = xr[lane + 32*i]; s += v[i].x + v[i].y + v[i].z + v[i].w; }
    #pragma unroll
    for (int o = 16; o > 0; o >>= 1) s += __shfl_xor_sync(0xffffffffu, s, o);
    const float mu = s * (1.0f / DMODEL);
    float q = 0.f;
    #pragma unroll
    for (int i = 0; i < 4; i++) {
        float d;
        d = v[i].x - mu; q += d*d;  d = v[i].y - mu; q += d*d;
        d = v[i].z - mu; q += d*d;  d = v[i].w - mu; q += d*d;
    }
    #pragma unroll
    for (int o = 16; o > 0; o >>= 1) q += __shfl_xor_sync(0xffffffffu, q, o);
    const float inv = rsqrtf(q * (1.0f / DMODEL) + 1e-5f);
    const float4* s4 = (const float4*)sc;
    const float4* b4 = (const float4*)bi;
    __half2* o2 = (__half2*)(out + (size_t)row * DMODEL);
    #pragma unroll
    for (int i = 0; i < 4; i++) {
        const int cc = lane + 32*i;
        float4 sv = s4[cc], bv = b4[cc];
        float rx = (v[i].x - mu) * inv * sv.x + bv.x;
        float ry = (v[i].y - mu) * inv * sv.y + bv.y;
        float rz = (v[i].z - mu) * inv * sv.z + bv.z;
        float rw = (v[i].w - mu) * inv * sv.w + bv.w;
        o2[2*cc]   = __floats2half2_rn(rx, ry);
        o2[2*cc+1] = __floats2half2_rn(rz, rw);
    }
}

// -----------------------------------------------------------------------------
extern "C" void kernel_launch(void* const* d_in, const int* in_sizes, int n_in,
                              void* d_out, int out_size)
{
    const float* frames    = (const float*)d_in[0];
    const int*   mask      = (const int*)d_in[1];
    const float* W_in_proj = (const float*)d_in[2];
    const float* b_in_proj = (const float*)d_in[3];
    const float* pos_emb   = (const float*)d_in[4];
    const float* ln_scale  = (const float*)d_in[5];
    const float* ln_bias   = (const float*)d_in[6];
    const float* W_in      = (const float*)d_in[7];
    const float* b_in      = (const float*)d_in[8];
    const float* W_out     = (const float*)d_in[9];
    const float* b_out     = (const float*)d_in[10];
    const float* fn_scale  = (const float*)d_in[11];
    const float* fn_bias   = (const float*)d_in[12];
    const float* W_frame   = (const float*)d_in[13];
    const float* b_frame   = (const float*)d_in[14];
    const float* W_sym     = (const float*)d_in[15];
    const float* b_sym     = (const float*)d_in[16];

    float *px, *pbh;
    __half *pn, *ph, *pfr, *pbtP, *pbtI, *pbtO, *pwht;
    cudaGetSymbolAddress((void**)&px,   g_x);
    cudaGetSymbolAddress((void**)&pn,   g_n);
    cudaGetSymbolAddress((void**)&ph,   g_h);
    cudaGetSymbolAddress((void**)&pfr,  g_fr);
    cudaGetSymbolAddress((void**)&pbtP, g_bt_inproj);
    cudaGetSymbolAddress((void**)&pbtI, g_bt_win);
    cudaGetSymbolAddress((void**)&pbtO, g_bt_wout);
    cudaGetSymbolAddress((void**)&pwht, g_wh_t);
    cudaGetSymbolAddress((void**)&pbh,  g_bh);

    float* out_frame = (float*)d_out;
    float* out_sym   = (float*)d_out + (size_t)NTOK * FDIM;

    cudaFuncSetAttribute(gemm_mma<1>, cudaFuncAttributeMaxDynamicSharedMemorySize, SMEM_BYTES);
    cudaFuncSetAttribute(gemm_mma<2>, cudaFuncAttributeMaxDynamicSharedMemorySize, SMEM_BYTES);
    cudaFuncSetAttribute(gemm_mma<3>, cudaFuncAttributeMaxDynamicSharedMemorySize, SMEM_BYTES);
    cudaFuncSetAttribute(gemm_mma<4>, cudaFuncAttributeMaxDynamicSharedMemorySize, SMEM_BYTES);

    // ---- weight & input prep (fp16) ----
    {
        dim3 b(32, 8);
        transpose_k<<<dim3(DMODEL/32, FDIM/32), b>>>(W_in_proj, pbtP, FDIM, DMODEL);
        for (int l = 0; l < NLAYERS; l++) {
            transpose_k<<<dim3(2*DINNER/32, DMODEL/32), b>>>(
                W_in + (size_t)l * DMODEL * 2 * DINNER,
                pbtI + (size_t)l * 2 * DINNER * DMODEL, DMODEL, 2*DINNER);
            transpose_k<<<dim3(DMODEL/32, DINNER/32), b>>>(
                W_out + (size_t)l * DINNER * DMODEL,
                pbtO + (size_t)l * DMODEL * DINNER, DINNER, DMODEL);
        }
        pack_heads_t<<<(DMODEL*NHEADS + 255)/256, 256>>>(W_frame, b_frame, W_sym, b_sym, pwht, pbh);
        conv_h<<<(NTOK*FDIM/4 + 255)/256, 256>>>(frames, pfr, NTOK*FDIM/4);
    }

    const dim3 lnb(32, 8);
    const int  lng = NTOK / 8;

    // 1) in_proj + pos_emb
    gemm_mma<1><<<dim3(DMODEL/128, NTOK/128), 256, SMEM_BYTES>>>(
        pfr, pbtP, b_in_proj, px, FDIM, DMODEL, pos_emb, nullptr, nullptr);

    // 2) layers: LN -> fused GEMM+GLU -> GEMM+residual
    for (int l = 0; l < NLAYERS; l++) {
        ln_kernel<<<lng, lnb>>>(px, ln_scale + l*DMODEL, ln_bias + l*DMODEL, pn);

        gemm_mma<4><<<dim3(DINNER/64, NTOK/128), 256, SMEM_BYTES>>>(
            pn, pbtI + (size_t)l * 2*DINNER*DMODEL,
            b_in + (size_t)l * 2*DINNER, (float*)ph, DMODEL, DINNER,
            nullptr, nullptr, nullptr);

        gemm_mma<2><<<dim3(DMODEL/128, NTOK/128), 256, SMEM_BYTES>>>(
            ph, pbtO + (size_t)l * DMODEL*DINNER,
            b_out + (size_t)l * DMODEL, px, DINNER, DMODEL,
            px, nullptr, nullptr);
    }

    // 3) final LN
    ln_kernel<<<lng, lnb>>>(px, fn_scale, fn_bias, pn);

    // 4) heads
    gemm_mma<3><<<dim3(NHEADS/128, NTOK/128), 256, SMEM_BYTES>>>(
        pn, pwht, pbh, out_frame, DMODEL, NHEADS,
        nullptr, mask, out_sym);
}